// round 2
// baseline (speedup 1.0000x reference)
#include <cuda_runtime.h>
#include <math.h>

#define BATCH  2
#define SEQ    2048
#define HIDDEN 2048
#define NHEAD  16
#define HDIM   128
#define MROWS  (BATCH*SEQ)   /* 4096 */

#define BQ 64
#define BKT 64
#define ATTN_SCALE 0.08838834764831845f  /* 1/sqrt(128) */

// ---------------- scratch (no allocations allowed) ----------------
__device__ float g_Q[(size_t)MROWS * HIDDEN];   // 33.5 MB
__device__ float g_K[(size_t)MROWS * HDIM];     //  2 MB
__device__ float g_V[(size_t)MROWS * HDIM];     //  2 MB
__device__ float g_attn[(size_t)MROWS * HIDDEN];// 33.5 MB

// ---------------- SGEMM: C[M,N] = A[M,K] @ B[K,N] + bias ----------------
// 128x128 tile, BK=16, 256 threads, 8x8 per-thread microtile.
__global__ __launch_bounds__(256) void sgemm_bias(
    const float* __restrict__ A, const float* __restrict__ B,
    const float* __restrict__ bias, float* __restrict__ C,
    int M, int N, int K)
{
    __shared__ float As[16][132];   // [BK][BM+4], A stored transposed
    __shared__ float Bs[16][132];   // [BK][BN+4]

    const int tid = threadIdx.x;
    const int tx = tid & 15;
    const int ty = tid >> 4;
    const int row0 = blockIdx.y * 128;
    const int col0 = blockIdx.x * 128;

    const float* Ab = A + (size_t)row0 * K;
    const float* Bb = B + col0;

    float acc[8][8];
#pragma unroll
    for (int i = 0; i < 8; i++)
#pragma unroll
        for (int j = 0; j < 8; j++) acc[i][j] = 0.f;

    const int ar = tid >> 2;          // 0..63
    const int ac = (tid & 3) * 4;     // 0,4,8,12
    const int br = tid >> 5;          // 0..7
    const int bc = (tid & 31) * 4;    // 0..124

    for (int k0 = 0; k0 < K; k0 += 16) {
#pragma unroll
        for (int rr = 0; rr < 2; rr++) {
            float4 a4 = *(const float4*)(Ab + (size_t)(ar + rr * 64) * K + k0 + ac);
            As[ac + 0][ar + rr * 64] = a4.x;
            As[ac + 1][ar + rr * 64] = a4.y;
            As[ac + 2][ar + rr * 64] = a4.z;
            As[ac + 3][ar + rr * 64] = a4.w;
        }
#pragma unroll
        for (int rr = 0; rr < 2; rr++) {
            float4 b4 = *(const float4*)(Bb + (size_t)(k0 + br + rr * 8) * N + bc);
            *(float4*)&Bs[br + rr * 8][bc] = b4;
        }
        __syncthreads();

#pragma unroll
        for (int k = 0; k < 16; k++) {
            float ra[8], rb[8];
            *(float4*)&ra[0] = *(const float4*)&As[k][ty * 8];
            *(float4*)&ra[4] = *(const float4*)&As[k][ty * 8 + 4];
            *(float4*)&rb[0] = *(const float4*)&Bs[k][tx * 8];
            *(float4*)&rb[4] = *(const float4*)&Bs[k][tx * 8 + 4];
#pragma unroll
            for (int i = 0; i < 8; i++)
#pragma unroll
                for (int j = 0; j < 8; j++)
                    acc[i][j] = fmaf(ra[i], rb[j], acc[i][j]);
        }
        __syncthreads();
    }

    float* Cb = C + (size_t)row0 * N + col0;
#pragma unroll
    for (int i = 0; i < 8; i++) {
        int r = ty * 8 + i;
#pragma unroll
        for (int j4 = 0; j4 < 8; j4 += 4) {
            float4 o;
            o.x = acc[i][j4 + 0] + bias[col0 + tx * 8 + j4 + 0];
            o.y = acc[i][j4 + 1] + bias[col0 + tx * 8 + j4 + 1];
            o.z = acc[i][j4 + 2] + bias[col0 + tx * 8 + j4 + 2];
            o.w = acc[i][j4 + 3] + bias[col0 + tx * 8 + j4 + 3];
            *(float4*)(Cb + (size_t)r * N + tx * 8 + j4) = o;
        }
    }
}

// ---------------- flash attention (fp32, online softmax) ----------------
struct AttnSmem {
    float qT[HDIM][BQ + 1];    // Q^T  (d-major) for QK^T
    float kT[HDIM][BKT + 1];   // K^T
    float v[BKT][HDIM + 4];
    float p[BQ][BKT + 1];
    float padf[BKT];
    float row_m[BQ];
    float row_l[BQ];
    float row_a[BQ];
};

__global__ __launch_bounds__(256) void attn_kernel(const float* __restrict__ pad_mask)
{
    extern __shared__ char smraw[];
    AttnSmem& sm = *reinterpret_cast<AttnSmem*>(smraw);

    const int qt = blockIdx.x;
    const int h  = blockIdx.y;
    const int b  = blockIdx.z;
    const int q0 = qt * BQ;
    const int tid = threadIdx.x;
    const int tx = tid & 15;
    const int ty = tid >> 4;

    // load Q tile (transposed into SMEM)
    const float* Qb = g_Q + (size_t)(b * SEQ + q0) * HIDDEN + h * HDIM;
    for (int i = tid; i < BQ * HDIM / 4; i += 256) {
        int r = i >> 5;
        int d = (i & 31) * 4;
        float4 q4 = *(const float4*)(Qb + (size_t)r * HIDDEN + d);
        sm.qT[d + 0][r] = q4.x; sm.qT[d + 1][r] = q4.y;
        sm.qT[d + 2][r] = q4.z; sm.qT[d + 3][r] = q4.w;
    }
    if (tid < BQ) { sm.row_m[tid] = -INFINITY; sm.row_l[tid] = 0.f; }

    float acc[4][8];
#pragma unroll
    for (int i = 0; i < 4; i++)
#pragma unroll
        for (int j = 0; j < 8; j++) acc[i][j] = 0.f;

    for (int kt = 0; kt <= qt; kt++) {
        const int k0 = kt * BKT;
        __syncthreads();  // guards Q/stat init on iter 0, and v/p/padf reuse after

        const float* Kb = g_K + (size_t)(b * SEQ + k0) * HDIM;
        const float* Vb = g_V + (size_t)(b * SEQ + k0) * HDIM;
        for (int i = tid; i < BKT * HDIM / 4; i += 256) {
            int r = i >> 5;
            int d = (i & 31) * 4;
            float4 k4 = *(const float4*)(Kb + (size_t)r * HDIM + d);
            sm.kT[d + 0][r] = k4.x; sm.kT[d + 1][r] = k4.y;
            sm.kT[d + 2][r] = k4.z; sm.kT[d + 3][r] = k4.w;
            float4 v4 = *(const float4*)(Vb + (size_t)r * HDIM + d);
            *(float4*)&sm.v[r][d] = v4;
        }
        if (tid < BKT) sm.padf[tid] = pad_mask[b * SEQ + k0 + tid];
        __syncthreads();

        // S = Q K^T  (4x4 microtile)
        float s[4][4];
#pragma unroll
        for (int i = 0; i < 4; i++)
#pragma unroll
            for (int j = 0; j < 4; j++) s[i][j] = 0.f;

        for (int d = 0; d < HDIM; d++) {
            float qa[4], kb[4];
#pragma unroll
            for (int i = 0; i < 4; i++) qa[i] = sm.qT[d][ty * 4 + i];
#pragma unroll
            for (int j = 0; j < 4; j++) kb[j] = sm.kT[d][tx * 4 + j];
#pragma unroll
            for (int i = 0; i < 4; i++)
#pragma unroll
                for (int j = 0; j < 4; j++)
                    s[i][j] = fmaf(qa[i], kb[j], s[i][j]);
        }

        // mask (causal analytic + pad from array) + scale; row max
        float rmax[4];
#pragma unroll
        for (int i = 0; i < 4; i++) {
            int qi = q0 + ty * 4 + i;
            rmax[i] = -INFINITY;
#pragma unroll
            for (int j = 0; j < 4; j++) {
                int kj = k0 + tx * 4 + j;
                bool ok = (kj <= qi) && (sm.padf[tx * 4 + j] < 0.5f);
                s[i][j] = ok ? s[i][j] * ATTN_SCALE : -1e30f;
                rmax[i] = fmaxf(rmax[i], s[i][j]);
            }
        }
        // reduce over the 16 threads sharing a row group
        for (int off = 8; off; off >>= 1)
#pragma unroll
            for (int i = 0; i < 4; i++)
                rmax[i] = fmaxf(rmax[i], __shfl_xor_sync(0xffffffffu, rmax[i], off));

        if (tx == 0) {
#pragma unroll
            for (int i = 0; i < 4; i++) {
                int r = ty * 4 + i;
                float m_old = sm.row_m[r];
                float m_new = fmaxf(m_old, rmax[i]);
                sm.row_a[r] = __expf(m_old - m_new);   // exp(-inf)=0 on first tile
                sm.row_m[r] = m_new;
            }
        }
        __syncthreads();

        float rsum[4] = {0.f, 0.f, 0.f, 0.f};
#pragma unroll
        for (int i = 0; i < 4; i++) {
            float m = sm.row_m[ty * 4 + i];
#pragma unroll
            for (int j = 0; j < 4; j++) {
                float p = __expf(s[i][j] - m);
                sm.p[ty * 4 + i][tx * 4 + j] = p;
                rsum[i] += p;
            }
        }
        for (int off = 8; off; off >>= 1)
#pragma unroll
            for (int i = 0; i < 4; i++)
                rsum[i] += __shfl_xor_sync(0xffffffffu, rsum[i], off);
        if (tx == 0) {
#pragma unroll
            for (int i = 0; i < 4; i++) {
                int r = ty * 4 + i;
                sm.row_l[r] = sm.row_l[r] * sm.row_a[r] + rsum[i];
            }
        }
        // rescale running O by alpha BEFORE adding this tile's PV
#pragma unroll
        for (int i = 0; i < 4; i++) {
            float a = sm.row_a[ty * 4 + i];
#pragma unroll
            for (int j = 0; j < 8; j++) acc[i][j] *= a;
        }
        __syncthreads();  // p fully written

        // O += P @ V   (4 rows x 8 cols per thread)
        for (int k = 0; k < BKT; k++) {
            float rp[4], rv[8];
#pragma unroll
            for (int i = 0; i < 4; i++) rp[i] = sm.p[ty * 4 + i][k];
            *(float4*)&rv[0] = *(const float4*)&sm.v[k][tx * 8];
            *(float4*)&rv[4] = *(const float4*)&sm.v[k][tx * 8 + 4];
#pragma unroll
            for (int i = 0; i < 4; i++)
#pragma unroll
                for (int j = 0; j < 8; j++)
                    acc[i][j] = fmaf(rp[i], rv[j], acc[i][j]);
        }
    }

    // epilogue: normalize and write to [B,S,NH,HD] layout (== [B,S,HID])
    float* Ob = g_attn + (size_t)(b * SEQ + q0) * HIDDEN + h * HDIM;
#pragma unroll
    for (int i = 0; i < 4; i++) {
        int r = ty * 4 + i;
        float inv = 1.f / sm.row_l[r];
        float4 o1, o2;
        o1.x = acc[i][0] * inv; o1.y = acc[i][1] * inv;
        o1.z = acc[i][2] * inv; o1.w = acc[i][3] * inv;
        o2.x = acc[i][4] * inv; o2.y = acc[i][5] * inv;
        o2.z = acc[i][6] * inv; o2.w = acc[i][7] * inv;
        *(float4*)(Ob + (size_t)r * HIDDEN + tx * 8)     = o1;
        *(float4*)(Ob + (size_t)r * HIDDEN + tx * 8 + 4) = o2;
    }
}

// ---------------- launch ----------------
extern "C" void kernel_launch(void* const* d_in, const int* in_sizes, int n_in,
                              void* d_out, int out_size)
{
    (void)in_sizes; (void)n_in; (void)out_size;

    const float* X   = (const float*)d_in[0];
    // d_in[1] = causal mask (strict triu) — reproduced analytically
    const float* pad = (const float*)d_in[2];
    const float* Wq  = (const float*)d_in[3];
    const float* bq  = (const float*)d_in[4];
    const float* Wk  = (const float*)d_in[5];
    const float* bk  = (const float*)d_in[6];
    const float* Wv  = (const float*)d_in[7];
    const float* bv  = (const float*)d_in[8];
    const float* Wo  = (const float*)d_in[9];
    const float* bo  = (const float*)d_in[10];
    float* out = (float*)d_out;

    float *Qp, *Kp, *Vp, *Ap;
    cudaGetSymbolAddress((void**)&Qp, g_Q);
    cudaGetSymbolAddress((void**)&Kp, g_K);
    cudaGetSymbolAddress((void**)&Vp, g_V);
    cudaGetSymbolAddress((void**)&Ap, g_attn);

    cudaFuncSetAttribute(attn_kernel, cudaFuncAttributeMaxDynamicSharedMemorySize,
                         (int)sizeof(AttnSmem));

    dim3 thr(256);
    // projections
    sgemm_bias<<<dim3(HIDDEN / 128, MROWS / 128), thr>>>(X, Wq, bq, Qp, MROWS, HIDDEN, HIDDEN);
    sgemm_bias<<<dim3(HDIM   / 128, MROWS / 128), thr>>>(X, Wk, bk, Kp, MROWS, HDIM,   HIDDEN);
    sgemm_bias<<<dim3(HDIM   / 128, MROWS / 128), thr>>>(X, Wv, bv, Vp, MROWS, HDIM,   HIDDEN);
    // attention
    attn_kernel<<<dim3(SEQ / BQ, NHEAD, BATCH), thr, sizeof(AttnSmem)>>>(pad);
    // output projection
    sgemm_bias<<<dim3(HIDDEN / 128, MROWS / 128), thr>>>(Ap, Wo, bo, out, MROWS, HIDDEN, HIDDEN);
}

// round 4
// speedup vs baseline: 1.4948x; 1.4948x over previous
#include <cuda_runtime.h>
#include <cuda_bf16.h>
#include <math.h>
#include <stdint.h>

#define BATCH  2
#define SEQ    2048
#define HIDDEN 2048
#define NHEAD  16
#define HDIM   128
#define MROWS  (BATCH*SEQ)   /* 4096 */

#define BQ 64
#define BKT 64
#define ATTN_SCALE 0.08838834764831845f  /* 1/sqrt(128) */

// ================= helpers =================
__device__ __forceinline__ uint32_t smem_u32(const void* p) {
    uint32_t a;
    asm("{ .reg .u64 t; cvta.to.shared.u64 t, %1; cvt.u32.u64 %0, t; }" : "=r"(a) : "l"(p));
    return a;
}

#define CP_ASYNC16(dst, src) \
    asm volatile("cp.async.cg.shared.global [%0], [%1], 16;" :: "r"(dst), "l"(src))
#define CP_COMMIT() asm volatile("cp.async.commit_group;" ::: "memory")
#define CP_WAIT1()  asm volatile("cp.async.wait_group 1;" ::: "memory")
#define CP_WAIT0()  asm volatile("cp.async.wait_group 0;" ::: "memory")

#define LDM4(r, addr)                                                        \
    asm volatile("ldmatrix.sync.aligned.m8n8.x4.shared.b16 {%0,%1,%2,%3}, [%4];" \
        : "=r"((r)[0]), "=r"((r)[1]), "=r"((r)[2]), "=r"((r)[3]) : "r"(addr))

#define MMA16816(d, a, b)                                                    \
    asm volatile("mma.sync.aligned.m16n8k16.row.col.f32.bf16.bf16.f32 "      \
        "{%0,%1,%2,%3}, {%4,%5,%6,%7}, {%8,%9}, {%0,%1,%2,%3};"              \
        : "+f"((d)[0]), "+f"((d)[1]), "+f"((d)[2]), "+f"((d)[3])             \
        : "r"((a)[0]), "r"((a)[1]), "r"((a)[2]), "r"((a)[3]),                \
          "r"((b)[0]), "r"((b)[1]))

// ================= scratch =================
__device__ float g_Q[(size_t)MROWS * HIDDEN];
__device__ float g_KV[(size_t)MROWS * 256];      // cols 0..127 = K, 128..255 = V
__device__ float g_attn[(size_t)MROWS * HIDDEN];
__device__ float g_bkv[256];
__device__ __nv_bfloat16 g_xhi[(size_t)MROWS * HIDDEN];
__device__ __nv_bfloat16 g_xlo[(size_t)MROWS * HIDDEN];
__device__ __nv_bfloat16 g_ahi[(size_t)MROWS * HIDDEN];
__device__ __nv_bfloat16 g_alo[(size_t)MROWS * HIDDEN];
__device__ __nv_bfloat16 g_wqT_hi[(size_t)HIDDEN * HIDDEN];
__device__ __nv_bfloat16 g_wqT_lo[(size_t)HIDDEN * HIDDEN];
__device__ __nv_bfloat16 g_wkvT_hi[(size_t)256 * HIDDEN];
__device__ __nv_bfloat16 g_wkvT_lo[(size_t)256 * HIDDEN];
__device__ __nv_bfloat16 g_woT_hi[(size_t)HIDDEN * HIDDEN];
__device__ __nv_bfloat16 g_woT_lo[(size_t)HIDDEN * HIDDEN];

// ================= prep: fp32 -> bf16 hi/lo split =================
__global__ void split_kernel(const float* __restrict__ x,
                             __nv_bfloat16* __restrict__ hi,
                             __nv_bfloat16* __restrict__ lo, int n4) {
    int i = blockIdx.x * blockDim.x + threadIdx.x;
    if (i >= n4) return;
    float4 v = ((const float4*)x)[i];
    __nv_bfloat16 h0 = __float2bfloat16(v.x), h1 = __float2bfloat16(v.y);
    __nv_bfloat16 h2 = __float2bfloat16(v.z), h3 = __float2bfloat16(v.w);
    __nv_bfloat16 l0 = __float2bfloat16(v.x - __bfloat162float(h0));
    __nv_bfloat16 l1 = __float2bfloat16(v.y - __bfloat162float(h1));
    __nv_bfloat16 l2 = __float2bfloat16(v.z - __bfloat162float(h2));
    __nv_bfloat16 l3 = __float2bfloat16(v.w - __bfloat162float(h3));
    __nv_bfloat162* hp = (__nv_bfloat162*)hi;
    __nv_bfloat162* lp = (__nv_bfloat162*)lo;
    hp[i * 2 + 0] = __nv_bfloat162(h0, h1);
    hp[i * 2 + 1] = __nv_bfloat162(h2, h3);
    lp[i * 2 + 0] = __nv_bfloat162(l0, l1);
    lp[i * 2 + 1] = __nv_bfloat162(l2, l3);
}

// ================= prep: W[K,N] fp32 -> Wt[N,K] bf16 hi/lo =================
__global__ void transpose_split(const float* __restrict__ W,
                                __nv_bfloat16* __restrict__ Thi,
                                __nv_bfloat16* __restrict__ Tlo, int K, int N) {
    __shared__ float t[32][33];
    int k0 = blockIdx.y * 32, n0 = blockIdx.x * 32;
    int tx = threadIdx.x, ty = threadIdx.y;
#pragma unroll
    for (int i = 0; i < 4; i++)
        t[ty + i * 8][tx] = W[(size_t)(k0 + ty + i * 8) * N + n0 + tx];
    __syncthreads();
#pragma unroll
    for (int i = 0; i < 4; i++) {
        float v = t[tx][ty + i * 8];
        __nv_bfloat16 h = __float2bfloat16(v);
        size_t idx = (size_t)(n0 + ty + i * 8) * K + k0 + tx;
        Thi[idx] = h;
        Tlo[idx] = __float2bfloat16(v - __bfloat162float(h));
    }
}

__global__ void pack_bias(const float* __restrict__ bk, const float* __restrict__ bv) {
    int t = threadIdx.x;
    g_bkv[t] = (t < 128) ? bk[t] : bv[t - 128];
}

// ================= split-bf16 GEMM via mma.sync (HMMA) =================
// C[M,N] = A[M,K] @ Bt[N,K]^T + bias ; three bf16 passes into fp32 regs.
// CTA tile 128x128, BK=32, 8 warps (2x4), 64x32 per warp.
#define GK 32
#define ROWB 80                          /* bytes per smem row: 32 bf16 + 8 pad */
#define TILE_B (128 * ROWB)              /* 10240 */
#define STAGE_B (4 * TILE_B)             /* Ahi Alo Bhi Blo = 40960 */
#define GEMM_SMEM (2 * STAGE_B)          /* 81920 */

__global__ __launch_bounds__(256) void gemm_split(
    const __nv_bfloat16* __restrict__ Ahi, const __nv_bfloat16* __restrict__ Alo,
    const __nv_bfloat16* __restrict__ Bhi, const __nv_bfloat16* __restrict__ Blo,
    const float* __restrict__ bias, float* __restrict__ C, int N, int K)
{
    extern __shared__ char sm[];
    const uint32_t smb = smem_u32(sm);
    const int tid = threadIdx.x;
    const int wid = tid >> 5;
    const int lane = tid & 31;
    const int wr = wid >> 2;            // 0..1
    const int wc = wid & 3;             // 0..3
    const int row0 = blockIdx.y * 128;
    const int col0 = blockIdx.x * 128;
    const int NC = K / GK;

    const __nv_bfloat16* srcs[4] = {
        Ahi + (size_t)row0 * K, Alo + (size_t)row0 * K,
        Bhi + (size_t)col0 * K, Blo + (size_t)col0 * K };

    // per-thread load coords: 512 x 16B per tile, 2 per thread per tile
    const int lr0 = tid >> 2;                 // 0..63
    const int lc  = (tid & 3) << 3;           // 0,8,16,24 (bf16 idx)

    float acc[4][4][4];
#pragma unroll
    for (int mi = 0; mi < 4; mi++)
#pragma unroll
        for (int ni = 0; ni < 4; ni++)
#pragma unroll
            for (int e = 0; e < 4; e++) acc[mi][ni][e] = 0.f;

    // prologue: load chunk 0
    {
        const uint32_t stage = smb;
#pragma unroll
        for (int t = 0; t < 4; t++) {
            const __nv_bfloat16* s = srcs[t];
#pragma unroll
            for (int v = 0; v < 2; v++) {
                int r = lr0 + v * 64;
                CP_ASYNC16(stage + t * TILE_B + r * ROWB + lc * 2,
                           s + (size_t)r * K + lc);
            }
        }
        CP_COMMIT();
    }

    for (int c = 0; c < NC; c++) {
        const int buf = c & 1;
        if (c + 1 < NC) {
            const uint32_t stage = smb + ((c + 1) & 1) * STAGE_B;
            const int k0 = (c + 1) * GK;
#pragma unroll
            for (int t = 0; t < 4; t++) {
                const __nv_bfloat16* s = srcs[t] + k0;
#pragma unroll
                for (int v = 0; v < 2; v++) {
                    int r = lr0 + v * 64;
                    CP_ASYNC16(stage + t * TILE_B + r * ROWB + lc * 2,
                               s + (size_t)r * K + lc);
                }
            }
            CP_COMMIT();
            CP_WAIT1();
        } else {
            CP_WAIT0();
        }
        __syncthreads();

        const uint32_t sA_h = smb + buf * STAGE_B;
        const uint32_t sA_l = sA_h + TILE_B;
        const uint32_t sB_h = sA_h + 2 * TILE_B;
        const uint32_t sB_l = sA_h + 3 * TILE_B;

#pragma unroll
        for (int ks = 0; ks < 2; ks++) {
            uint32_t ah[4][4], al[4][4], bh[4][2], bl[4][2];
            const int acol = ks * 32 + (lane >> 4) * 16;   // bytes
#pragma unroll
            for (int mi = 0; mi < 4; mi++) {
                uint32_t ra = (uint32_t)((wr * 64 + mi * 16 + (lane & 15)) * ROWB + acol);
                LDM4(ah[mi], sA_h + ra);
                LDM4(al[mi], sA_l + ra);
            }
            const int bcol = ks * 32 + ((lane >> 3) & 1) * 16;  // bytes
            const int brow = (lane & 7) + ((lane >> 4) << 3);
#pragma unroll
            for (int nh = 0; nh < 2; nh++) {
                uint32_t rb = (uint32_t)((wc * 32 + nh * 16 + brow) * ROWB + bcol);
                uint32_t t4[4];
                LDM4(t4, sB_h + rb);
                bh[nh * 2 + 0][0] = t4[0]; bh[nh * 2 + 0][1] = t4[1];
                bh[nh * 2 + 1][0] = t4[2]; bh[nh * 2 + 1][1] = t4[3];
                LDM4(t4, sB_l + rb);
                bl[nh * 2 + 0][0] = t4[0]; bl[nh * 2 + 0][1] = t4[1];
                bl[nh * 2 + 1][0] = t4[2]; bl[nh * 2 + 1][1] = t4[3];
            }
#pragma unroll
            for (int mi = 0; mi < 4; mi++)
#pragma unroll
                for (int ni = 0; ni < 4; ni++) {
                    MMA16816(acc[mi][ni], ah[mi], bh[ni]);
                    MMA16816(acc[mi][ni], ah[mi], bl[ni]);
                    MMA16816(acc[mi][ni], al[mi], bh[ni]);
                }
        }
        __syncthreads();
    }

    // epilogue
#pragma unroll
    for (int mi = 0; mi < 4; mi++) {
        int r = row0 + wr * 64 + mi * 16 + (lane >> 2);
#pragma unroll
        for (int ni = 0; ni < 4; ni++) {
            int cc = col0 + wc * 32 + ni * 8 + (lane & 3) * 2;
            float b0 = bias[cc], b1 = bias[cc + 1];
            float2 o0 = make_float2(acc[mi][ni][0] + b0, acc[mi][ni][1] + b1);
            float2 o1 = make_float2(acc[mi][ni][2] + b0, acc[mi][ni][3] + b1);
            *(float2*)(C + (size_t)r * N + cc) = o0;
            *(float2*)(C + (size_t)(r + 8) * N + cc) = o1;
        }
    }
}

// ================= flash attention (fp32) =================
struct AttnSmem {
    float qT[HDIM][BQ + 1];
    float kT[HDIM][BKT + 1];
    float v[BKT][HDIM + 4];
    float p[BQ][BKT + 1];
    float padf[BKT];
    float row_m[BQ];
    float row_l[BQ];
    float row_a[BQ];
};

__global__ __launch_bounds__(256) void attn_kernel(const float* __restrict__ pad_mask)
{
    extern __shared__ char smraw[];
    AttnSmem& sm = *reinterpret_cast<AttnSmem*>(smraw);

    const int qt = blockIdx.x;
    const int h  = blockIdx.y;
    const int b  = blockIdx.z;
    const int q0 = qt * BQ;
    const int tid = threadIdx.x;
    const int tx = tid & 15;
    const int ty = tid >> 4;

    const float* Qb = g_Q + (size_t)(b * SEQ + q0) * HIDDEN + h * HDIM;
    for (int i = tid; i < BQ * HDIM / 4; i += 256) {
        int r = i >> 5;
        int d = (i & 31) * 4;
        float4 q4 = *(const float4*)(Qb + (size_t)r * HIDDEN + d);
        sm.qT[d + 0][r] = q4.x; sm.qT[d + 1][r] = q4.y;
        sm.qT[d + 2][r] = q4.z; sm.qT[d + 3][r] = q4.w;
    }
    if (tid < BQ) { sm.row_m[tid] = -INFINITY; sm.row_l[tid] = 0.f; }

    float acc[4][8];
#pragma unroll
    for (int i = 0; i < 4; i++)
#pragma unroll
        for (int j = 0; j < 8; j++) acc[i][j] = 0.f;

    for (int kt = 0; kt <= qt; kt++) {
        const int k0 = kt * BKT;
        __syncthreads();

        const float* KVb = g_KV + (size_t)(b * SEQ + k0) * 256;
        for (int i = tid; i < BKT * HDIM / 4; i += 256) {
            int r = i >> 5;
            int d = (i & 31) * 4;
            float4 k4 = *(const float4*)(KVb + (size_t)r * 256 + d);
            sm.kT[d + 0][r] = k4.x; sm.kT[d + 1][r] = k4.y;
            sm.kT[d + 2][r] = k4.z; sm.kT[d + 3][r] = k4.w;
            float4 v4 = *(const float4*)(KVb + (size_t)r * 256 + 128 + d);
            *(float4*)&sm.v[r][d] = v4;
        }
        if (tid < BKT) sm.padf[tid] = pad_mask[b * SEQ + k0 + tid];
        __syncthreads();

        float s[4][4];
#pragma unroll
        for (int i = 0; i < 4; i++)
#pragma unroll
            for (int j = 0; j < 4; j++) s[i][j] = 0.f;

        for (int d = 0; d < HDIM; d++) {
            float qa[4], kb[4];
#pragma unroll
            for (int i = 0; i < 4; i++) qa[i] = sm.qT[d][ty * 4 + i];
#pragma unroll
            for (int j = 0; j < 4; j++) kb[j] = sm.kT[d][tx * 4 + j];
#pragma unroll
            for (int i = 0; i < 4; i++)
#pragma unroll
                for (int j = 0; j < 4; j++)
                    s[i][j] = fmaf(qa[i], kb[j], s[i][j]);
        }

        float rmax[4];
#pragma unroll
        for (int i = 0; i < 4; i++) {
            int qi = q0 + ty * 4 + i;
            rmax[i] = -INFINITY;
#pragma unroll
            for (int j = 0; j < 4; j++) {
                int kj = k0 + tx * 4 + j;
                bool ok = (kj <= qi) && (sm.padf[tx * 4 + j] < 0.5f);
                s[i][j] = ok ? s[i][j] * ATTN_SCALE : -1e30f;
                rmax[i] = fmaxf(rmax[i], s[i][j]);
            }
        }
        for (int off = 8; off; off >>= 1)
#pragma unroll
            for (int i = 0; i < 4; i++)
                rmax[i] = fmaxf(rmax[i], __shfl_xor_sync(0xffffffffu, rmax[i], off));

        if (tx == 0) {
#pragma unroll
            for (int i = 0; i < 4; i++) {
                int r = ty * 4 + i;
                float m_old = sm.row_m[r];
                float m_new = fmaxf(m_old, rmax[i]);
                sm.row_a[r] = __expf(m_old - m_new);
                sm.row_m[r] = m_new;
            }
        }
        __syncthreads();

        float rsum[4] = {0.f, 0.f, 0.f, 0.f};
#pragma unroll
        for (int i = 0; i < 4; i++) {
            float m = sm.row_m[ty * 4 + i];
#pragma unroll
            for (int j = 0; j < 4; j++) {
                float p = __expf(s[i][j] - m);
                sm.p[ty * 4 + i][tx * 4 + j] = p;
                rsum[i] += p;
            }
        }
        for (int off = 8; off; off >>= 1)
#pragma unroll
            for (int i = 0; i < 4; i++)
                rsum[i] += __shfl_xor_sync(0xffffffffu, rsum[i], off);
        if (tx == 0) {
#pragma unroll
            for (int i = 0; i < 4; i++) {
                int r = ty * 4 + i;
                sm.row_l[r] = sm.row_l[r] * sm.row_a[r] + rsum[i];
            }
        }
#pragma unroll
        for (int i = 0; i < 4; i++) {
            float a = sm.row_a[ty * 4 + i];
#pragma unroll
            for (int j = 0; j < 8; j++) acc[i][j] *= a;
        }
        __syncthreads();

        for (int k = 0; k < BKT; k++) {
            float rp[4], rv[8];
#pragma unroll
            for (int i = 0; i < 4; i++) rp[i] = sm.p[ty * 4 + i][k];
            *(float4*)&rv[0] = *(const float4*)&sm.v[k][tx * 8];
            *(float4*)&rv[4] = *(const float4*)&sm.v[k][tx * 8 + 4];
#pragma unroll
            for (int i = 0; i < 4; i++)
#pragma unroll
                for (int j = 0; j < 8; j++)
                    acc[i][j] = fmaf(rp[i], rv[j], acc[i][j]);
        }
    }

    float* Ob = g_attn + (size_t)(b * SEQ + q0) * HIDDEN + h * HDIM;
#pragma unroll
    for (int i = 0; i < 4; i++) {
        int r = ty * 4 + i;
        float inv = 1.f / sm.row_l[r];
        float4 o1, o2;
        o1.x = acc[i][0] * inv; o1.y = acc[i][1] * inv;
        o1.z = acc[i][2] * inv; o1.w = acc[i][3] * inv;
        o2.x = acc[i][4] * inv; o2.y = acc[i][5] * inv;
        o2.z = acc[i][6] * inv; o2.w = acc[i][7] * inv;
        *(float4*)(Ob + (size_t)r * HIDDEN + tx * 8)     = o1;
        *(float4*)(Ob + (size_t)r * HIDDEN + tx * 8 + 4) = o2;
    }
}

// ================= launch =================
extern "C" void kernel_launch(void* const* d_in, const int* in_sizes, int n_in,
                              void* d_out, int out_size)
{
    (void)in_sizes; (void)n_in; (void)out_size;

    const float* X   = (const float*)d_in[0];
    const float* pad = (const float*)d_in[2];
    const float* Wq  = (const float*)d_in[3];
    const float* bq  = (const float*)d_in[4];
    const float* Wk  = (const float*)d_in[5];
    const float* bk  = (const float*)d_in[6];
    const float* Wv  = (const float*)d_in[7];
    const float* bv  = (const float*)d_in[8];
    const float* Wo  = (const float*)d_in[9];
    const float* bo  = (const float*)d_in[10];
    float* out = (float*)d_out;

    float *Qp, *KVp, *Ap, *bkvp;
    __nv_bfloat16 *xhi, *xlo, *ahi, *alo;
    __nv_bfloat16 *wqh, *wql, *wkvh, *wkvl, *woh, *wol;
    cudaGetSymbolAddress((void**)&Qp, g_Q);
    cudaGetSymbolAddress((void**)&KVp, g_KV);
    cudaGetSymbolAddress((void**)&Ap, g_attn);
    cudaGetSymbolAddress((void**)&bkvp, g_bkv);
    cudaGetSymbolAddress((void**)&xhi, g_xhi);
    cudaGetSymbolAddress((void**)&xlo, g_xlo);
    cudaGetSymbolAddress((void**)&ahi, g_ahi);
    cudaGetSymbolAddress((void**)&alo, g_alo);
    cudaGetSymbolAddress((void**)&wqh, g_wqT_hi);
    cudaGetSymbolAddress((void**)&wql, g_wqT_lo);
    cudaGetSymbolAddress((void**)&wkvh, g_wkvT_hi);
    cudaGetSymbolAddress((void**)&wkvl, g_wkvT_lo);
    cudaGetSymbolAddress((void**)&woh, g_woT_hi);
    cudaGetSymbolAddress((void**)&wol, g_woT_lo);

    cudaFuncSetAttribute(attn_kernel, cudaFuncAttributeMaxDynamicSharedMemorySize,
                         (int)sizeof(AttnSmem));
    cudaFuncSetAttribute(gemm_split, cudaFuncAttributeMaxDynamicSharedMemorySize,
                         GEMM_SMEM);

    // --- prep ---
    {
        int n4 = MROWS * HIDDEN / 4;
        split_kernel<<<(n4 + 255) / 256, 256>>>(X, xhi, xlo, n4);
    }
    transpose_split<<<dim3(HIDDEN / 32, HIDDEN / 32), dim3(32, 8)>>>(Wq, wqh, wql, HIDDEN, HIDDEN);
    transpose_split<<<dim3(HDIM / 32,   HIDDEN / 32), dim3(32, 8)>>>(Wk, wkvh, wkvl, HIDDEN, HDIM);
    transpose_split<<<dim3(HDIM / 32,   HIDDEN / 32), dim3(32, 8)>>>(
        Wv, wkvh + (size_t)128 * HIDDEN, wkvl + (size_t)128 * HIDDEN, HIDDEN, HDIM);
    transpose_split<<<dim3(HIDDEN / 32, HIDDEN / 32), dim3(32, 8)>>>(Wo, woh, wol, HIDDEN, HIDDEN);
    pack_bias<<<1, 256>>>(bk, bv);

    // --- projections (HMMA split-bf16) ---
    gemm_split<<<dim3(HIDDEN / 128, MROWS / 128), 256, GEMM_SMEM>>>(
        xhi, xlo, wqh, wql, bq, Qp, HIDDEN, HIDDEN);
    gemm_split<<<dim3(256 / 128, MROWS / 128), 256, GEMM_SMEM>>>(
        xhi, xlo, wkvh, wkvl, bkvp, KVp, 256, HIDDEN);

    // --- attention ---
    attn_kernel<<<dim3(SEQ / BQ, NHEAD, BATCH), 256, sizeof(AttnSmem)>>>(pad);

    // --- output projection ---
    {
        int n4 = MROWS * HIDDEN / 4;
        split_kernel<<<(n4 + 255) / 256, 256>>>(Ap, ahi, alo, n4);
    }
    gemm_split<<<dim3(HIDDEN / 128, MROWS / 128), 256, GEMM_SMEM>>>(
        ahi, alo, woh, wol, bo, out, HIDDEN, HIDDEN);
}

// round 5
// speedup vs baseline: 1.9493x; 1.3041x over previous
#include <cuda_runtime.h>
#include <cuda_bf16.h>
#include <math.h>
#include <stdint.h>

#define BATCH  2
#define SEQ    2048
#define HIDDEN 2048
#define NHEAD  16
#define HDIM   128
#define MROWS  (BATCH*SEQ)   /* 4096 */
#define ATTN_SCALE 0.08838834764831845f  /* 1/sqrt(128) */

// ================= helpers =================
__device__ __forceinline__ uint32_t smem_u32(const void* p) {
    uint32_t a;
    asm("{ .reg .u64 t; cvta.to.shared.u64 t, %1; cvt.u32.u64 %0, t; }" : "=r"(a) : "l"(p));
    return a;
}

#define CP_ASYNC16(dst, src) \
    asm volatile("cp.async.cg.shared.global [%0], [%1], 16;" :: "r"(dst), "l"(src))
#define CP_COMMIT() asm volatile("cp.async.commit_group;" ::: "memory")
#define CP_WAIT1()  asm volatile("cp.async.wait_group 1;" ::: "memory")
#define CP_WAIT0()  asm volatile("cp.async.wait_group 0;" ::: "memory")

#define LDM4(r, addr)                                                        \
    asm volatile("ldmatrix.sync.aligned.m8n8.x4.shared.b16 {%0,%1,%2,%3}, [%4];" \
        : "=r"((r)[0]), "=r"((r)[1]), "=r"((r)[2]), "=r"((r)[3]) : "r"(addr))

#define MMA16816(d, a, b)                                                    \
    asm volatile("mma.sync.aligned.m16n8k16.row.col.f32.bf16.bf16.f32 "      \
        "{%0,%1,%2,%3}, {%4,%5,%6,%7}, {%8,%9}, {%0,%1,%2,%3};"              \
        : "+f"((d)[0]), "+f"((d)[1]), "+f"((d)[2]), "+f"((d)[3])             \
        : "r"((a)[0]), "r"((a)[1]), "r"((a)[2]), "r"((a)[3]),                \
          "r"((b)[0]), "r"((b)[1]))

__device__ __forceinline__ uint32_t pack_bf2(float lo, float hi) {
    uint32_t r;
    asm("cvt.rn.bf16x2.f32 %0, %1, %2;" : "=r"(r) : "f"(hi), "f"(lo));
    return r;
}
__device__ __forceinline__ float bf2lo(uint32_t u) {
    __nv_bfloat162 v = *(__nv_bfloat162*)&u; return __bfloat162float(v.x);
}
__device__ __forceinline__ float bf2hi(uint32_t u) {
    __nv_bfloat162 v = *(__nv_bfloat162*)&u; return __bfloat162float(v.y);
}

// ================= scratch =================
__device__ float g_bkv[256];
__device__ __nv_bfloat16 g_xhi[(size_t)MROWS * HIDDEN];
__device__ __nv_bfloat16 g_xlo[(size_t)MROWS * HIDDEN];
__device__ __nv_bfloat16 g_qhi[(size_t)MROWS * HIDDEN];   // pre-scaled Q
__device__ __nv_bfloat16 g_qlo[(size_t)MROWS * HIDDEN];
__device__ __nv_bfloat16 g_kvhi[(size_t)MROWS * 256];     // cols 0..127 K, 128..255 V
__device__ __nv_bfloat16 g_kvlo[(size_t)MROWS * 256];
__device__ __nv_bfloat16 g_vthi[(size_t)BATCH * HDIM * SEQ]; // [b][d][seq]
__device__ __nv_bfloat16 g_vtlo[(size_t)BATCH * HDIM * SEQ];
__device__ __nv_bfloat16 g_ahi[(size_t)MROWS * HIDDEN];   // attention output
__device__ __nv_bfloat16 g_alo[(size_t)MROWS * HIDDEN];
__device__ __nv_bfloat16 g_wqT_hi[(size_t)HIDDEN * HIDDEN];
__device__ __nv_bfloat16 g_wqT_lo[(size_t)HIDDEN * HIDDEN];
__device__ __nv_bfloat16 g_wkvT_hi[(size_t)256 * HIDDEN];
__device__ __nv_bfloat16 g_wkvT_lo[(size_t)256 * HIDDEN];
__device__ __nv_bfloat16 g_woT_hi[(size_t)HIDDEN * HIDDEN];
__device__ __nv_bfloat16 g_woT_lo[(size_t)HIDDEN * HIDDEN];

// ================= prep kernels =================
__global__ void split_kernel(const float* __restrict__ x,
                             __nv_bfloat16* __restrict__ hi,
                             __nv_bfloat16* __restrict__ lo, int n4) {
    int i = blockIdx.x * blockDim.x + threadIdx.x;
    if (i >= n4) return;
    float4 v = ((const float4*)x)[i];
    __nv_bfloat16 h0 = __float2bfloat16(v.x), h1 = __float2bfloat16(v.y);
    __nv_bfloat16 h2 = __float2bfloat16(v.z), h3 = __float2bfloat16(v.w);
    __nv_bfloat16 l0 = __float2bfloat16(v.x - __bfloat162float(h0));
    __nv_bfloat16 l1 = __float2bfloat16(v.y - __bfloat162float(h1));
    __nv_bfloat16 l2 = __float2bfloat16(v.z - __bfloat162float(h2));
    __nv_bfloat16 l3 = __float2bfloat16(v.w - __bfloat162float(h3));
    __nv_bfloat162* hp = (__nv_bfloat162*)hi;
    __nv_bfloat162* lp = (__nv_bfloat162*)lo;
    hp[i * 2 + 0] = __nv_bfloat162(h0, h1);
    hp[i * 2 + 1] = __nv_bfloat162(h2, h3);
    lp[i * 2 + 0] = __nv_bfloat162(l0, l1);
    lp[i * 2 + 1] = __nv_bfloat162(l2, l3);
}

__global__ void transpose_split(const float* __restrict__ W,
                                __nv_bfloat16* __restrict__ Thi,
                                __nv_bfloat16* __restrict__ Tlo, int K, int N) {
    __shared__ float t[32][33];
    int k0 = blockIdx.y * 32, n0 = blockIdx.x * 32;
    int tx = threadIdx.x, ty = threadIdx.y;
#pragma unroll
    for (int i = 0; i < 4; i++)
        t[ty + i * 8][tx] = W[(size_t)(k0 + ty + i * 8) * N + n0 + tx];
    __syncthreads();
#pragma unroll
    for (int i = 0; i < 4; i++) {
        float v = t[tx][ty + i * 8];
        __nv_bfloat16 h = __float2bfloat16(v);
        size_t idx = (size_t)(n0 + ty + i * 8) * K + k0 + tx;
        Thi[idx] = h;
        Tlo[idx] = __float2bfloat16(v - __bfloat162float(h));
    }
}

__global__ void pack_bias(const float* __restrict__ bk, const float* __restrict__ bv) {
    int t = threadIdx.x;
    g_bkv[t] = (t < 128) ? bk[t] : bv[t - 128];
}

// build Vt[b][d][seq] bf16 hi/lo from g_kv{hi,lo} (V = cols 128..255)
__global__ void vt_prep() {
    __shared__ __nv_bfloat16 th[32][33], tl[32][33];
    int s0 = blockIdx.x * 32;
    int d0 = blockIdx.y * 32;
    int tx = threadIdx.x, ty = threadIdx.y;
#pragma unroll
    for (int i = 0; i < 4; i++) {
        int row = s0 + ty + 8 * i;
        th[ty + 8 * i][tx] = g_kvhi[(size_t)row * 256 + 128 + d0 + tx];
        tl[ty + 8 * i][tx] = g_kvlo[(size_t)row * 256 + 128 + d0 + tx];
    }
    __syncthreads();
    int bb = s0 >> 11;
    int seq = s0 & 2047;
#pragma unroll
    for (int i = 0; i < 4; i++) {
        int d = d0 + ty + 8 * i;
        g_vthi[((size_t)(bb * HDIM) + d) * SEQ + seq + tx] = th[tx][ty + 8 * i];
        g_vtlo[((size_t)(bb * HDIM) + d) * SEQ + seq + tx] = tl[tx][ty + 8 * i];
    }
}

// ================= split-bf16 GEMM (HMMA) =================
// MODE 0: C = f32 (acc + bias). MODE 1: Ohi/Olo = split bf16 of (acc+bias)*scale.
#define GK 32
#define ROWB 80
#define TILE_B (128 * ROWB)
#define STAGE_B (4 * TILE_B)
#define GEMM_SMEM (2 * STAGE_B)

template<int MODE>
__global__ __launch_bounds__(256) void gemm_split(
    const __nv_bfloat16* __restrict__ Ahi, const __nv_bfloat16* __restrict__ Alo,
    const __nv_bfloat16* __restrict__ Bhi, const __nv_bfloat16* __restrict__ Blo,
    const float* __restrict__ bias, float* __restrict__ C,
    __nv_bfloat16* __restrict__ Ohi, __nv_bfloat16* __restrict__ Olo,
    float scale, int N, int K)
{
    extern __shared__ char sm[];
    const uint32_t smb = smem_u32(sm);
    const int tid = threadIdx.x;
    const int wid = tid >> 5;
    const int lane = tid & 31;
    const int wr = wid >> 2;
    const int wc = wid & 3;
    const int row0 = blockIdx.y * 128;
    const int col0 = blockIdx.x * 128;
    const int NC = K / GK;

    const __nv_bfloat16* srcs[4] = {
        Ahi + (size_t)row0 * K, Alo + (size_t)row0 * K,
        Bhi + (size_t)col0 * K, Blo + (size_t)col0 * K };

    const int lr0 = tid >> 2;
    const int lc  = (tid & 3) << 3;

    float acc[4][4][4];
#pragma unroll
    for (int mi = 0; mi < 4; mi++)
#pragma unroll
        for (int ni = 0; ni < 4; ni++)
#pragma unroll
            for (int e = 0; e < 4; e++) acc[mi][ni][e] = 0.f;

    {
        const uint32_t stage = smb;
#pragma unroll
        for (int t = 0; t < 4; t++) {
            const __nv_bfloat16* s = srcs[t];
#pragma unroll
            for (int v = 0; v < 2; v++) {
                int r = lr0 + v * 64;
                CP_ASYNC16(stage + t * TILE_B + r * ROWB + lc * 2,
                           s + (size_t)r * K + lc);
            }
        }
        CP_COMMIT();
    }

    for (int c = 0; c < NC; c++) {
        const int buf = c & 1;
        if (c + 1 < NC) {
            const uint32_t stage = smb + ((c + 1) & 1) * STAGE_B;
            const int k0 = (c + 1) * GK;
#pragma unroll
            for (int t = 0; t < 4; t++) {
                const __nv_bfloat16* s = srcs[t] + k0;
#pragma unroll
                for (int v = 0; v < 2; v++) {
                    int r = lr0 + v * 64;
                    CP_ASYNC16(stage + t * TILE_B + r * ROWB + lc * 2,
                               s + (size_t)r * K + lc);
                }
            }
            CP_COMMIT();
            CP_WAIT1();
        } else {
            CP_WAIT0();
        }
        __syncthreads();

        const uint32_t sA_h = smb + buf * STAGE_B;
        const uint32_t sA_l = sA_h + TILE_B;
        const uint32_t sB_h = sA_h + 2 * TILE_B;
        const uint32_t sB_l = sA_h + 3 * TILE_B;

#pragma unroll
        for (int ks = 0; ks < 2; ks++) {
            uint32_t ah[4][4], al[4][4], bh[4][2], bl[4][2];
            const int acol = ks * 32 + (lane >> 4) * 16;
#pragma unroll
            for (int mi = 0; mi < 4; mi++) {
                uint32_t ra = (uint32_t)((wr * 64 + mi * 16 + (lane & 15)) * ROWB + acol);
                LDM4(ah[mi], sA_h + ra);
                LDM4(al[mi], sA_l + ra);
            }
            const int bcol = ks * 32 + ((lane >> 3) & 1) * 16;
            const int brow = (lane & 7) + ((lane >> 4) << 3);
#pragma unroll
            for (int nh = 0; nh < 2; nh++) {
                uint32_t rb = (uint32_t)((wc * 32 + nh * 16 + brow) * ROWB + bcol);
                uint32_t t4[4];
                LDM4(t4, sB_h + rb);
                bh[nh * 2 + 0][0] = t4[0]; bh[nh * 2 + 0][1] = t4[1];
                bh[nh * 2 + 1][0] = t4[2]; bh[nh * 2 + 1][1] = t4[3];
                LDM4(t4, sB_l + rb);
                bl[nh * 2 + 0][0] = t4[0]; bl[nh * 2 + 0][1] = t4[1];
                bl[nh * 2 + 1][0] = t4[2]; bl[nh * 2 + 1][1] = t4[3];
            }
#pragma unroll
            for (int mi = 0; mi < 4; mi++)
#pragma unroll
                for (int ni = 0; ni < 4; ni++) {
                    MMA16816(acc[mi][ni], ah[mi], bh[ni]);
                    MMA16816(acc[mi][ni], ah[mi], bl[ni]);
                    MMA16816(acc[mi][ni], al[mi], bh[ni]);
                }
        }
        __syncthreads();
    }

#pragma unroll
    for (int mi = 0; mi < 4; mi++) {
        int r = row0 + wr * 64 + mi * 16 + (lane >> 2);
#pragma unroll
        for (int ni = 0; ni < 4; ni++) {
            int cc = col0 + wc * 32 + ni * 8 + (lane & 3) * 2;
            float b0 = bias[cc], b1 = bias[cc + 1];
            if (MODE == 0) {
                float2 o0 = make_float2(acc[mi][ni][0] + b0, acc[mi][ni][1] + b1);
                float2 o1 = make_float2(acc[mi][ni][2] + b0, acc[mi][ni][3] + b1);
                *(float2*)(C + (size_t)r * N + cc) = o0;
                *(float2*)(C + (size_t)(r + 8) * N + cc) = o1;
            } else {
                float v0 = (acc[mi][ni][0] + b0) * scale;
                float v1 = (acc[mi][ni][1] + b1) * scale;
                float v2 = (acc[mi][ni][2] + b0) * scale;
                float v3 = (acc[mi][ni][3] + b1) * scale;
                uint32_t h0 = pack_bf2(v0, v1);
                uint32_t l0 = pack_bf2(v0 - bf2lo(h0), v1 - bf2hi(h0));
                uint32_t h1 = pack_bf2(v2, v3);
                uint32_t l1 = pack_bf2(v2 - bf2lo(h1), v3 - bf2hi(h1));
                *(uint32_t*)((char*)Ohi + ((size_t)r * N + cc) * 2) = h0;
                *(uint32_t*)((char*)Olo + ((size_t)r * N + cc) * 2) = l0;
                *(uint32_t*)((char*)Ohi + ((size_t)(r + 8) * N + cc) * 2) = h1;
                *(uint32_t*)((char*)Olo + ((size_t)(r + 8) * N + cc) * 2) = l1;
            }
        }
    }
}

// ================= tensor-core flash attention =================
// BQ=128 (8 warps x 16 rows), BKT=64. Split-bf16 3-pass S and PV.
#define KPITCH 272
#define VPITCH 144
#define AT_OFF_KHI  0
#define AT_OFF_KLO  17408
#define AT_OFF_VTHI 34816
#define AT_OFF_VTLO 53248
#define AT_STAGE    71680
#define AT_OFF_PAD  (2 * AT_STAGE)
#define AT_SMEM     (AT_OFF_PAD + 512)

__global__ __launch_bounds__(256) void attn_tc(const float* __restrict__ pad_mask)
{
    extern __shared__ char sm[];
    const uint32_t smb = smem_u32(sm);
    float* padS = (float*)(sm + AT_OFF_PAD);

    const int qt = 15 - (int)blockIdx.x;     // heavy tiles first
    const int h  = blockIdx.y;
    const int b  = blockIdx.z;
    const int q0 = qt * 128;
    const int tid = threadIdx.x;
    const int w = tid >> 5, lane = tid & 31;
    const int g = lane >> 2, t = lane & 3;
    const int rw = q0 + 16 * w;
    const int last_kt = 2 * qt + 1;

    const int brow = (lane & 7) + ((lane >> 4) << 3);
    const int bcol = ((lane >> 3) & 1) * 16;

    // ---- Q fragments, straight 4B loads from pre-scaled split-bf16 Q ----
    uint32_t qh[8][4], ql[8][4];
    {
        const size_t r0 = (size_t)(b * SEQ + rw + g) * HIDDEN + h * HDIM;
        const size_t r8 = r0 + (size_t)8 * HIDDEN;
#pragma unroll
        for (int kf = 0; kf < 8; kf++) {
            int c0 = kf * 16 + 2 * t;
            qh[kf][0] = *(const uint32_t*)((const char*)g_qhi + (r0 + c0) * 2);
            qh[kf][1] = *(const uint32_t*)((const char*)g_qhi + (r8 + c0) * 2);
            qh[kf][2] = *(const uint32_t*)((const char*)g_qhi + (r0 + c0 + 8) * 2);
            qh[kf][3] = *(const uint32_t*)((const char*)g_qhi + (r8 + c0 + 8) * 2);
            ql[kf][0] = *(const uint32_t*)((const char*)g_qlo + (r0 + c0) * 2);
            ql[kf][1] = *(const uint32_t*)((const char*)g_qlo + (r8 + c0) * 2);
            ql[kf][2] = *(const uint32_t*)((const char*)g_qlo + (r0 + c0 + 8) * 2);
            ql[kf][3] = *(const uint32_t*)((const char*)g_qlo + (r8 + c0 + 8) * 2);
        }
    }

    float m0 = -INFINITY, m1 = -INFINITY, l0 = 0.f, l1 = 0.f;
    float o[16][4];
#pragma unroll
    for (int oj = 0; oj < 16; oj++)
#pragma unroll
        for (int e = 0; e < 4; e++) o[oj][e] = 0.f;

    auto fill = [&](int kt, int buf) {
        const int k0 = kt * 64;
        const uint32_t st = smb + buf * AT_STAGE;
        const char* khiG = (const char*)g_kvhi + (size_t)(b * SEQ + k0) * 512;
        const char* kloG = (const char*)g_kvlo + (size_t)(b * SEQ + k0) * 512;
        const char* vhiG = (const char*)g_vthi + ((size_t)(b * HDIM) * SEQ + k0) * 2;
        const char* vloG = (const char*)g_vtlo + ((size_t)(b * HDIM) * SEQ + k0) * 2;
#pragma unroll
        for (int v = 0; v < 4; v++) {
            int c = v * 256 + tid;
            int kr = c >> 4, kc = c & 15;
            CP_ASYNC16(st + AT_OFF_KHI + kr * KPITCH + kc * 16, khiG + (size_t)kr * 512 + kc * 16);
            CP_ASYNC16(st + AT_OFF_KLO + kr * KPITCH + kc * 16, kloG + (size_t)kr * 512 + kc * 16);
            int dr = c >> 3, dc = c & 7;
            CP_ASYNC16(st + AT_OFF_VTHI + dr * VPITCH + dc * 16, vhiG + (size_t)dr * (SEQ * 2) + dc * 16);
            CP_ASYNC16(st + AT_OFF_VTLO + dr * VPITCH + dc * 16, vloG + (size_t)dr * (SEQ * 2) + dc * 16);
        }
        if (tid < 64) padS[buf * 64 + tid] = pad_mask[b * SEQ + k0 + tid];
        CP_COMMIT();
    };

    fill(0, 0);

    for (int kt = 0; kt <= last_kt; kt++) {
        const int buf = kt & 1;
        const int k0 = kt * 64;
        if (kt < last_kt) { fill(kt + 1, buf ^ 1); CP_WAIT1(); }
        else              { CP_WAIT0(); }
        __syncthreads();

        if (k0 <= rw + 15) {   // warp-uniform
            const uint32_t st = smb + buf * AT_STAGE;

            // ---- S = Q K^T (3-pass) ----
            float s[8][4];
#pragma unroll
            for (int ni = 0; ni < 8; ni++)
#pragma unroll
                for (int e = 0; e < 4; e++) s[ni][e] = 0.f;

#pragma unroll
            for (int nj = 0; nj < 4; nj++) {
                const uint32_t roff = (uint32_t)((16 * nj + brow) * KPITCH + bcol);
#pragma unroll
                for (int kf = 0; kf < 8; kf++) {
                    uint32_t addr = st + AT_OFF_KHI + roff + kf * 32;
                    uint32_t bh[4], bl[4];
                    LDM4(bh, addr);
                    LDM4(bl, addr + (AT_OFF_KLO - AT_OFF_KHI));
                    MMA16816(s[2 * nj],     qh[kf], bh);
                    MMA16816(s[2 * nj + 1], qh[kf], bh + 2);
                    MMA16816(s[2 * nj],     qh[kf], bl);
                    MMA16816(s[2 * nj + 1], qh[kf], bl + 2);
                    MMA16816(s[2 * nj],     ql[kf], bh);
                    MMA16816(s[2 * nj + 1], ql[kf], bh + 2);
                }
            }

            // ---- mask (pad always, causal on diagonal tiles) ----
            const float* pf = padS + buf * 64;
            const bool causal = (k0 + 63 > rw);
            const int rg = rw + g, rg8 = rg + 8;
#pragma unroll
            for (int ni = 0; ni < 8; ni++) {
                int c0 = ni * 8 + 2 * t, c1 = c0 + 1;
                bool p0 = pf[c0] < 0.5f, p1 = pf[c1] < 0.5f;
                bool ok0 = p0, ok1 = p1, ok2 = p0, ok3 = p1;
                if (causal) {
                    ok0 = ok0 && (k0 + c0 <= rg);
                    ok1 = ok1 && (k0 + c1 <= rg);
                    ok2 = ok2 && (k0 + c0 <= rg8);
                    ok3 = ok3 && (k0 + c1 <= rg8);
                }
                s[ni][0] = ok0 ? s[ni][0] : -INFINITY;
                s[ni][1] = ok1 ? s[ni][1] : -INFINITY;
                s[ni][2] = ok2 ? s[ni][2] : -INFINITY;
                s[ni][3] = ok3 ? s[ni][3] : -INFINITY;
            }

            // ---- online softmax (warp-local rows) ----
            float rm0 = -INFINITY, rm1 = -INFINITY;
#pragma unroll
            for (int ni = 0; ni < 8; ni++) {
                rm0 = fmaxf(rm0, fmaxf(s[ni][0], s[ni][1]));
                rm1 = fmaxf(rm1, fmaxf(s[ni][2], s[ni][3]));
            }
            rm0 = fmaxf(rm0, __shfl_xor_sync(0xffffffffu, rm0, 1));
            rm0 = fmaxf(rm0, __shfl_xor_sync(0xffffffffu, rm0, 2));
            rm1 = fmaxf(rm1, __shfl_xor_sync(0xffffffffu, rm1, 1));
            rm1 = fmaxf(rm1, __shfl_xor_sync(0xffffffffu, rm1, 2));
            float mn0 = fmaxf(m0, rm0), mn1 = fmaxf(m1, rm1);
            float a0 = __expf(m0 - mn0), a1 = __expf(m1 - mn1);
            m0 = mn0; m1 = mn1;

            float ls0 = 0.f, ls1 = 0.f;
#pragma unroll
            for (int ni = 0; ni < 8; ni++) {
                s[ni][0] = __expf(s[ni][0] - m0); ls0 += s[ni][0];
                s[ni][1] = __expf(s[ni][1] - m0); ls0 += s[ni][1];
                s[ni][2] = __expf(s[ni][2] - m1); ls1 += s[ni][2];
                s[ni][3] = __expf(s[ni][3] - m1); ls1 += s[ni][3];
            }
            ls0 += __shfl_xor_sync(0xffffffffu, ls0, 1);
            ls0 += __shfl_xor_sync(0xffffffffu, ls0, 2);
            ls1 += __shfl_xor_sync(0xffffffffu, ls1, 1);
            ls1 += __shfl_xor_sync(0xffffffffu, ls1, 2);
            l0 = l0 * a0 + ls0;
            l1 = l1 * a1 + ls1;
#pragma unroll
            for (int oj = 0; oj < 16; oj++) {
                o[oj][0] *= a0; o[oj][1] *= a0;
                o[oj][2] *= a1; o[oj][3] *= a1;
            }

            // ---- PV (3-pass), P stays in registers ----
#pragma unroll
            for (int kf = 0; kf < 4; kf++) {
                float p00 = s[2 * kf][0],     p01 = s[2 * kf][1];
                float p10 = s[2 * kf][2],     p11 = s[2 * kf][3];
                float p20 = s[2 * kf + 1][0], p21 = s[2 * kf + 1][1];
                float p30 = s[2 * kf + 1][2], p31 = s[2 * kf + 1][3];
                uint32_t ph[4], pl[4];
                ph[0] = pack_bf2(p00, p01);
                ph[1] = pack_bf2(p10, p11);
                ph[2] = pack_bf2(p20, p21);
                ph[3] = pack_bf2(p30, p31);
                pl[0] = pack_bf2(p00 - bf2lo(ph[0]), p01 - bf2hi(ph[0]));
                pl[1] = pack_bf2(p10 - bf2lo(ph[1]), p11 - bf2hi(ph[1]));
                pl[2] = pack_bf2(p20 - bf2lo(ph[2]), p21 - bf2hi(ph[2]));
                pl[3] = pack_bf2(p30 - bf2lo(ph[3]), p31 - bf2hi(ph[3]));
#pragma unroll
                for (int dj = 0; dj < 8; dj++) {
                    uint32_t addr = st + AT_OFF_VTHI +
                        (uint32_t)((16 * dj + brow) * VPITCH + kf * 32 + bcol);
                    uint32_t vh[4], vl[4];
                    LDM4(vh, addr);
                    LDM4(vl, addr + (AT_OFF_VTLO - AT_OFF_VTHI));
                    MMA16816(o[2 * dj],     ph, vh);
                    MMA16816(o[2 * dj + 1], ph, vh + 2);
                    MMA16816(o[2 * dj],     ph, vl);
                    MMA16816(o[2 * dj + 1], ph, vl + 2);
                    MMA16816(o[2 * dj],     pl, vh);
                    MMA16816(o[2 * dj + 1], pl, vh + 2);
                }
            }
        }
        __syncthreads();
    }

    // ---- epilogue: normalize, split to bf16 hi/lo for the O projection ----
    {
        float i0 = 1.f / l0, i1 = 1.f / l1;
        const size_t r0 = (size_t)(b * SEQ + rw + g) * HIDDEN + h * HDIM;
        const size_t r8 = r0 + (size_t)8 * HIDDEN;
#pragma unroll
        for (int oj = 0; oj < 16; oj++) {
            int c0 = oj * 8 + 2 * t;
            float v0 = o[oj][0] * i0, v1 = o[oj][1] * i0;
            float v2 = o[oj][2] * i1, v3 = o[oj][3] * i1;
            uint32_t h0 = pack_bf2(v0, v1);
            uint32_t l0p = pack_bf2(v0 - bf2lo(h0), v1 - bf2hi(h0));
            uint32_t h1 = pack_bf2(v2, v3);
            uint32_t l1p = pack_bf2(v2 - bf2lo(h1), v3 - bf2hi(h1));
            *(uint32_t*)((char*)g_ahi + (r0 + c0) * 2) = h0;
            *(uint32_t*)((char*)g_alo + (r0 + c0) * 2) = l0p;
            *(uint32_t*)((char*)g_ahi + (r8 + c0) * 2) = h1;
            *(uint32_t*)((char*)g_alo + (r8 + c0) * 2) = l1p;
        }
    }
}

// ================= launch =================
extern "C" void kernel_launch(void* const* d_in, const int* in_sizes, int n_in,
                              void* d_out, int out_size)
{
    (void)in_sizes; (void)n_in; (void)out_size;

    const float* X   = (const float*)d_in[0];
    const float* pad = (const float*)d_in[2];
    const float* Wq  = (const float*)d_in[3];
    const float* bq  = (const float*)d_in[4];
    const float* Wk  = (const float*)d_in[5];
    const float* bk  = (const float*)d_in[6];
    const float* Wv  = (const float*)d_in[7];
    const float* bv  = (const float*)d_in[8];
    const float* Wo  = (const float*)d_in[9];
    const float* bo  = (const float*)d_in[10];
    float* out = (float*)d_out;

    float* bkvp;
    __nv_bfloat16 *xhi, *xlo, *qhi, *qlo, *kvhi, *kvlo, *ahi, *alo;
    __nv_bfloat16 *wqh, *wql, *wkvh, *wkvl, *woh, *wol;
    cudaGetSymbolAddress((void**)&bkvp, g_bkv);
    cudaGetSymbolAddress((void**)&xhi, g_xhi);
    cudaGetSymbolAddress((void**)&xlo, g_xlo);
    cudaGetSymbolAddress((void**)&qhi, g_qhi);
    cudaGetSymbolAddress((void**)&qlo, g_qlo);
    cudaGetSymbolAddress((void**)&kvhi, g_kvhi);
    cudaGetSymbolAddress((void**)&kvlo, g_kvlo);
    cudaGetSymbolAddress((void**)&ahi, g_ahi);
    cudaGetSymbolAddress((void**)&alo, g_alo);
    cudaGetSymbolAddress((void**)&wqh, g_wqT_hi);
    cudaGetSymbolAddress((void**)&wql, g_wqT_lo);
    cudaGetSymbolAddress((void**)&wkvh, g_wkvT_hi);
    cudaGetSymbolAddress((void**)&wkvl, g_wkvT_lo);
    cudaGetSymbolAddress((void**)&woh, g_woT_hi);
    cudaGetSymbolAddress((void**)&wol, g_woT_lo);

    cudaFuncSetAttribute(gemm_split<0>, cudaFuncAttributeMaxDynamicSharedMemorySize, GEMM_SMEM);
    cudaFuncSetAttribute(gemm_split<1>, cudaFuncAttributeMaxDynamicSharedMemorySize, GEMM_SMEM);
    cudaFuncSetAttribute(attn_tc, cudaFuncAttributeMaxDynamicSharedMemorySize, AT_SMEM);

    // --- prep ---
    {
        int n4 = MROWS * HIDDEN / 4;
        split_kernel<<<(n4 + 255) / 256, 256>>>(X, xhi, xlo, n4);
    }
    transpose_split<<<dim3(HIDDEN / 32, HIDDEN / 32), dim3(32, 8)>>>(Wq, wqh, wql, HIDDEN, HIDDEN);
    transpose_split<<<dim3(HDIM / 32,   HIDDEN / 32), dim3(32, 8)>>>(Wk, wkvh, wkvl, HIDDEN, HDIM);
    transpose_split<<<dim3(HDIM / 32,   HIDDEN / 32), dim3(32, 8)>>>(
        Wv, wkvh + (size_t)128 * HIDDEN, wkvl + (size_t)128 * HIDDEN, HIDDEN, HDIM);
    transpose_split<<<dim3(HIDDEN / 32, HIDDEN / 32), dim3(32, 8)>>>(Wo, woh, wol, HIDDEN, HIDDEN);
    pack_bias<<<1, 256>>>(bk, bv);

    // --- projections ---
    gemm_split<1><<<dim3(HIDDEN / 128, MROWS / 128), 256, GEMM_SMEM>>>(
        xhi, xlo, wqh, wql, bq, nullptr, qhi, qlo, ATTN_SCALE, HIDDEN, HIDDEN);
    gemm_split<1><<<dim3(256 / 128, MROWS / 128), 256, GEMM_SMEM>>>(
        xhi, xlo, wkvh, wkvl, bkvp, nullptr, kvhi, kvlo, 1.0f, 256, HIDDEN);
    vt_prep<<<dim3(MROWS / 32, HDIM / 32), dim3(32, 8)>>>();

    // --- attention ---
    attn_tc<<<dim3(SEQ / 128, NHEAD, BATCH), 256, AT_SMEM>>>(pad);

    // --- output projection ---
    gemm_split<0><<<dim3(HIDDEN / 128, MROWS / 128), 256, GEMM_SMEM>>>(
        ahi, alo, woh, wol, bo, out, nullptr, nullptr, 1.0f, HIDDEN, HIDDEN);
}

// round 10
// speedup vs baseline: 3.6864x; 1.8912x over previous
#include <cuda_runtime.h>
#include <cuda_fp16.h>
#include <math.h>
#include <stdint.h>

#define BATCH  2
#define SEQ    2048
#define HIDDEN 2048
#define NHEAD  16
#define HDIM   128
#define MROWS  (BATCH*SEQ)   /* 4096 */
#define NQKV   2304          /* 2048 Q + 128 K + 128 V */
/* 1/sqrt(128) * log2(e): base-2 softmax, folded into Q projection */
#define QSCALE 0.12751744615329684f

// ================= helpers =================
__device__ __forceinline__ uint32_t smem_u32(const void* p) {
    uint32_t a;
    asm("{ .reg .u64 t; cvta.to.shared.u64 t, %1; cvt.u32.u64 %0, t; }" : "=r"(a) : "l"(p));
    return a;
}
__device__ __forceinline__ float ex2f(float x) {
    float r;
    asm("ex2.approx.f32 %0, %1;" : "=f"(r) : "f"(x));
    return r;
}

#define CP_ASYNC16(dst, src) \
    asm volatile("cp.async.cg.shared.global [%0], [%1], 16;" :: "r"(dst), "l"(src))
#define CP_COMMIT() asm volatile("cp.async.commit_group;" ::: "memory")
#define CP_WAIT1()  asm volatile("cp.async.wait_group 1;" ::: "memory")
#define CP_WAIT0()  asm volatile("cp.async.wait_group 0;" ::: "memory")

#define LDM4(r, addr)                                                        \
    asm volatile("ldmatrix.sync.aligned.m8n8.x4.shared.b16 {%0,%1,%2,%3}, [%4];" \
        : "=r"((r)[0]), "=r"((r)[1]), "=r"((r)[2]), "=r"((r)[3]) : "r"(addr))

#define MMA16816(d, a, b)                                                    \
    asm volatile("mma.sync.aligned.m16n8k16.row.col.f32.f16.f16.f32 "        \
        "{%0,%1,%2,%3}, {%4,%5,%6,%7}, {%8,%9}, {%0,%1,%2,%3};"              \
        : "+f"((d)[0]), "+f"((d)[1]), "+f"((d)[2]), "+f"((d)[3])             \
        : "r"((a)[0]), "r"((a)[1]), "r"((a)[2]), "r"((a)[3]),                \
          "r"((b)[0]), "r"((b)[1]))

__device__ __forceinline__ uint32_t pack_h2(float lo, float hi) {
    __half2 h = __floats2half2_rn(lo, hi);
    return *(uint32_t*)&h;
}
__device__ __forceinline__ float h2lo(uint32_t u) {
    __half2 v = *(__half2*)&u; return __low2float(v);
}
__device__ __forceinline__ float h2hi(uint32_t u) {
    __half2 v = *(__half2*)&u; return __high2float(v);
}

// ================= scratch =================
__device__ float g_bqkv[NQKV];
__device__ __half g_xhi[(size_t)MROWS * HIDDEN];
__device__ __half g_xlo[(size_t)MROWS * HIDDEN];
__device__ __half g_qkvhi[(size_t)MROWS * NQKV];   // Q pre-scaled | K | V
__device__ __half g_qkvlo[(size_t)MROWS * NQKV];
__device__ __half g_vthi[(size_t)BATCH * HDIM * SEQ]; // [b][d][seq]
__device__ __half g_vtlo[(size_t)BATCH * HDIM * SEQ];
__device__ __half g_ahi[(size_t)MROWS * HIDDEN];   // attention output
__device__ __half g_alo[(size_t)MROWS * HIDDEN];
__device__ __half g_wT_hi[(size_t)NQKV * HIDDEN];  // [WqT;WkT;WvT]
__device__ __half g_wT_lo[(size_t)NQKV * HIDDEN];
__device__ __half g_woT_hi[(size_t)HIDDEN * HIDDEN];
__device__ __half g_woT_lo[(size_t)HIDDEN * HIDDEN];

// ================= prep kernels =================
__global__ void split_kernel(const float* __restrict__ x,
                             __half* __restrict__ hi,
                             __half* __restrict__ lo, int n4) {
    int i = blockIdx.x * blockDim.x + threadIdx.x;
    if (i >= n4) return;
    float4 v = ((const float4*)x)[i];
    __half h0 = __float2half_rn(v.x), h1 = __float2half_rn(v.y);
    __half h2 = __float2half_rn(v.z), h3 = __float2half_rn(v.w);
    __half l0 = __float2half_rn(v.x - __half2float(h0));
    __half l1 = __float2half_rn(v.y - __half2float(h1));
    __half l2 = __float2half_rn(v.z - __half2float(h2));
    __half l3 = __float2half_rn(v.w - __half2float(h3));
    __half2* hp = (__half2*)hi;
    __half2* lp = (__half2*)lo;
    hp[i * 2 + 0] = __halves2half2(h0, h1);
    hp[i * 2 + 1] = __halves2half2(h2, h3);
    lp[i * 2 + 0] = __halves2half2(l0, l1);
    lp[i * 2 + 1] = __halves2half2(l2, l3);
}

__global__ void transpose_split(const float* __restrict__ W,
                                __half* __restrict__ Thi,
                                __half* __restrict__ Tlo, int K, int N) {
    __shared__ float t[32][33];
    int k0 = blockIdx.y * 32, n0 = blockIdx.x * 32;
    int tx = threadIdx.x, ty = threadIdx.y;
#pragma unroll
    for (int i = 0; i < 4; i++)
        t[ty + i * 8][tx] = W[(size_t)(k0 + ty + i * 8) * N + n0 + tx];
    __syncthreads();
#pragma unroll
    for (int i = 0; i < 4; i++) {
        float v = t[tx][ty + i * 8];
        __half h = __float2half_rn(v);
        size_t idx = (size_t)(n0 + ty + i * 8) * K + k0 + tx;
        Thi[idx] = h;
        Tlo[idx] = __float2half_rn(v - __half2float(h));
    }
}

__global__ void pack_bias_qkv(const float* __restrict__ bq,
                              const float* __restrict__ bk,
                              const float* __restrict__ bv) {
    int t = blockIdx.x * 256 + threadIdx.x;
    if (t < 2048) g_bqkv[t] = bq[t];
    else if (t < 2176) g_bqkv[t] = bk[t - 2048];
    else if (t < NQKV) g_bqkv[t] = bv[t - 2176];
}

// build Vt[b][d][seq] from g_qkv cols 2176..2303
__global__ void vt_prep() {
    __shared__ __half th[32][33], tl[32][33];
    int s0 = blockIdx.x * 32;
    int d0 = blockIdx.y * 32;
    int tx = threadIdx.x, ty = threadIdx.y;
#pragma unroll
    for (int i = 0; i < 4; i++) {
        int row = s0 + ty + 8 * i;
        th[ty + 8 * i][tx] = g_qkvhi[(size_t)row * NQKV + 2176 + d0 + tx];
        tl[ty + 8 * i][tx] = g_qkvlo[(size_t)row * NQKV + 2176 + d0 + tx];
    }
    __syncthreads();
    int bb = s0 >> 11;
    int seq = s0 & 2047;
#pragma unroll
    for (int i = 0; i < 4; i++) {
        int d = d0 + ty + 8 * i;
        g_vthi[((size_t)(bb * HDIM) + d) * SEQ + seq + tx] = th[tx][ty + 8 * i];
        g_vtlo[((size_t)(bb * HDIM) + d) * SEQ + seq + tx] = tl[tx][ty + 8 * i];
    }
}

// ================= split-fp16 GEMM (HMMA, 3-pass) =================
// MODE 0: C = f32 (acc+bias). MODE 1: hi/lo fp16 of (acc+bias)*(cc<scale_cols?scale:1)
#define GK 32
#define ROWB 80
#define TILE_B (128 * ROWB)
#define STAGE_B (4 * TILE_B)
#define GEMM_SMEM (2 * STAGE_B)

template<int MODE>
__global__ __launch_bounds__(256) void gemm_split(
    const __half* __restrict__ Ahi, const __half* __restrict__ Alo,
    const __half* __restrict__ Bhi, const __half* __restrict__ Blo,
    const float* __restrict__ bias, float* __restrict__ C,
    __half* __restrict__ Ohi, __half* __restrict__ Olo,
    float scale, int scale_cols, int N, int K)
{
    extern __shared__ char sm[];
    const uint32_t smb = smem_u32(sm);
    const int tid = threadIdx.x;
    const int wid = tid >> 5;
    const int lane = tid & 31;
    const int wr = wid >> 2;
    const int wc = wid & 3;
    const int row0 = blockIdx.y * 128;
    const int col0 = blockIdx.x * 128;
    const int NC = K / GK;

    const __half* srcs[4] = {
        Ahi + (size_t)row0 * K, Alo + (size_t)row0 * K,
        Bhi + (size_t)col0 * K, Blo + (size_t)col0 * K };

    const int lr0 = tid >> 2;
    const int lc  = (tid & 3) << 3;

    float acc[4][4][4];
#pragma unroll
    for (int mi = 0; mi < 4; mi++)
#pragma unroll
        for (int ni = 0; ni < 4; ni++)
#pragma unroll
            for (int e = 0; e < 4; e++) acc[mi][ni][e] = 0.f;

    {
        const uint32_t stage = smb;
#pragma unroll
        for (int t = 0; t < 4; t++) {
            const __half* s = srcs[t];
#pragma unroll
            for (int v = 0; v < 2; v++) {
                int r = lr0 + v * 64;
                CP_ASYNC16(stage + t * TILE_B + r * ROWB + lc * 2,
                           s + (size_t)r * K + lc);
            }
        }
        CP_COMMIT();
    }

    for (int c = 0; c < NC; c++) {
        const int buf = c & 1;
        if (c + 1 < NC) {
            const uint32_t stage = smb + ((c + 1) & 1) * STAGE_B;
            const int k0 = (c + 1) * GK;
#pragma unroll
            for (int t = 0; t < 4; t++) {
                const __half* s = srcs[t] + k0;
#pragma unroll
                for (int v = 0; v < 2; v++) {
                    int r = lr0 + v * 64;
                    CP_ASYNC16(stage + t * TILE_B + r * ROWB + lc * 2,
                               s + (size_t)r * K + lc);
                }
            }
            CP_COMMIT();
            CP_WAIT1();
        } else {
            CP_WAIT0();
        }
        __syncthreads();

        const uint32_t sA_h = smb + buf * STAGE_B;
        const uint32_t sA_l = sA_h + TILE_B;
        const uint32_t sB_h = sA_h + 2 * TILE_B;
        const uint32_t sB_l = sA_h + 3 * TILE_B;

#pragma unroll
        for (int ks = 0; ks < 2; ks++) {
            uint32_t ah[4][4], al[4][4], bh[4][2], bl[4][2];
            const int acol = ks * 32 + (lane >> 4) * 16;
#pragma unroll
            for (int mi = 0; mi < 4; mi++) {
                uint32_t ra = (uint32_t)((wr * 64 + mi * 16 + (lane & 15)) * ROWB + acol);
                LDM4(ah[mi], sA_h + ra);
                LDM4(al[mi], sA_l + ra);
            }
            const int bcol = ks * 32 + ((lane >> 3) & 1) * 16;
            const int brow = (lane & 7) + ((lane >> 4) << 3);
#pragma unroll
            for (int nh = 0; nh < 2; nh++) {
                uint32_t rb = (uint32_t)((wc * 32 + nh * 16 + brow) * ROWB + bcol);
                uint32_t t4[4];
                LDM4(t4, sB_h + rb);
                bh[nh * 2 + 0][0] = t4[0]; bh[nh * 2 + 0][1] = t4[1];
                bh[nh * 2 + 1][0] = t4[2]; bh[nh * 2 + 1][1] = t4[3];
                LDM4(t4, sB_l + rb);
                bl[nh * 2 + 0][0] = t4[0]; bl[nh * 2 + 0][1] = t4[1];
                bl[nh * 2 + 1][0] = t4[2]; bl[nh * 2 + 1][1] = t4[3];
            }
#pragma unroll
            for (int mi = 0; mi < 4; mi++)
#pragma unroll
                for (int ni = 0; ni < 4; ni++) {
                    MMA16816(acc[mi][ni], ah[mi], bh[ni]);
                    MMA16816(acc[mi][ni], ah[mi], bl[ni]);
                    MMA16816(acc[mi][ni], al[mi], bh[ni]);
                }
        }
        __syncthreads();
    }

#pragma unroll
    for (int mi = 0; mi < 4; mi++) {
        int r = row0 + wr * 64 + mi * 16 + (lane >> 2);
#pragma unroll
        for (int ni = 0; ni < 4; ni++) {
            int cc = col0 + wc * 32 + ni * 8 + (lane & 3) * 2;
            float b0 = bias[cc], b1 = bias[cc + 1];
            if (MODE == 0) {
                float2 o0 = make_float2(acc[mi][ni][0] + b0, acc[mi][ni][1] + b1);
                float2 o1 = make_float2(acc[mi][ni][2] + b0, acc[mi][ni][3] + b1);
                *(float2*)(C + (size_t)r * N + cc) = o0;
                *(float2*)(C + (size_t)(r + 8) * N + cc) = o1;
            } else {
                float sc = (cc < scale_cols) ? scale : 1.0f;
                float v0 = (acc[mi][ni][0] + b0) * sc;
                float v1 = (acc[mi][ni][1] + b1) * sc;
                float v2 = (acc[mi][ni][2] + b0) * sc;
                float v3 = (acc[mi][ni][3] + b1) * sc;
                uint32_t h0 = pack_h2(v0, v1);
                uint32_t l0 = pack_h2(v0 - h2lo(h0), v1 - h2hi(h0));
                uint32_t h1 = pack_h2(v2, v3);
                uint32_t l1 = pack_h2(v2 - h2lo(h1), v3 - h2hi(h1));
                *(uint32_t*)((char*)Ohi + ((size_t)r * N + cc) * 2) = h0;
                *(uint32_t*)((char*)Olo + ((size_t)r * N + cc) * 2) = l0;
                *(uint32_t*)((char*)Ohi + ((size_t)(r + 8) * N + cc) * 2) = h1;
                *(uint32_t*)((char*)Olo + ((size_t)(r + 8) * N + cc) * 2) = l1;
            }
        }
    }
}

// ================= tensor-core flash attention (fp16, 2-pass) =================
#define KPITCH 272
#define VPITCH 144
#define AT_OFF_KHI  0
#define AT_OFF_KLO  17408
#define AT_OFF_VTHI 34816
#define AT_OFF_VTLO 53248
#define AT_STAGE    71680
#define AT_OFF_PAD  (2 * AT_STAGE)
#define AT_SMEM     (AT_OFF_PAD + 512)

__global__ __launch_bounds__(256) void attn_tc(const float* __restrict__ pad_mask)
{
    extern __shared__ char sm[];
    const uint32_t smb = smem_u32(sm);
    float* padS = (float*)(sm + AT_OFF_PAD);

    // heavy qt first across ALL heads (best tail behavior)
    const int qt = 15 - ((int)blockIdx.x >> 4);
    const int h  = (int)blockIdx.x & 15;
    const int b  = blockIdx.z;
    const int q0 = qt * 128;
    const int tid = threadIdx.x;
    const int w = tid >> 5, lane = tid & 31;
    const int g = lane >> 2, t = lane & 3;
    const int rw = q0 + 16 * w;
    const int last_kt = 2 * qt + 1;

    const int brow = (lane & 7) + ((lane >> 4) << 3);
    const int bcol = ((lane >> 3) & 1) * 16;

    // ---- Q hi fragments only (lo pass dropped) ----
    uint32_t qh[8][4];
    {
        const size_t r0 = (size_t)(b * SEQ + rw + g) * NQKV + h * HDIM;
        const size_t r8 = r0 + (size_t)8 * NQKV;
#pragma unroll
        for (int kf = 0; kf < 8; kf++) {
            int c0 = kf * 16 + 2 * t;
            qh[kf][0] = *(const uint32_t*)((const char*)g_qkvhi + (r0 + c0) * 2);
            qh[kf][1] = *(const uint32_t*)((const char*)g_qkvhi + (r8 + c0) * 2);
            qh[kf][2] = *(const uint32_t*)((const char*)g_qkvhi + (r0 + c0 + 8) * 2);
            qh[kf][3] = *(const uint32_t*)((const char*)g_qkvhi + (r8 + c0 + 8) * 2);
        }
    }

    float m0 = -INFINITY, m1 = -INFINITY, l0 = 0.f, l1 = 0.f;
    float o[16][4];
#pragma unroll
    for (int oj = 0; oj < 16; oj++)
#pragma unroll
        for (int e = 0; e < 4; e++) o[oj][e] = 0.f;

    auto fill = [&](int kt, int buf) {
        const int k0 = kt * 64;
        const uint32_t st = smb + buf * AT_STAGE;
        const char* khiG = (const char*)g_qkvhi + ((size_t)(b * SEQ + k0) * NQKV + 2048) * 2;
        const char* kloG = (const char*)g_qkvlo + ((size_t)(b * SEQ + k0) * NQKV + 2048) * 2;
        const char* vhiG = (const char*)g_vthi + ((size_t)(b * HDIM) * SEQ + k0) * 2;
        const char* vloG = (const char*)g_vtlo + ((size_t)(b * HDIM) * SEQ + k0) * 2;
#pragma unroll
        for (int v = 0; v < 4; v++) {
            int c = v * 256 + tid;
            int kr = c >> 4, kc = c & 15;
            CP_ASYNC16(st + AT_OFF_KHI + kr * KPITCH + kc * 16, khiG + (size_t)kr * (NQKV * 2) + kc * 16);
            CP_ASYNC16(st + AT_OFF_KLO + kr * KPITCH + kc * 16, kloG + (size_t)kr * (NQKV * 2) + kc * 16);
            int dr = c >> 3, dc = c & 7;
            CP_ASYNC16(st + AT_OFF_VTHI + dr * VPITCH + dc * 16, vhiG + (size_t)dr * (SEQ * 2) + dc * 16);
            CP_ASYNC16(st + AT_OFF_VTLO + dr * VPITCH + dc * 16, vloG + (size_t)dr * (SEQ * 2) + dc * 16);
        }
        if (tid < 64) padS[buf * 64 + tid] = pad_mask[b * SEQ + k0 + tid];
        CP_COMMIT();
    };

    fill(0, 0);

    for (int kt = 0; kt <= last_kt; kt++) {
        const int buf = kt & 1;
        const int k0 = kt * 64;
        if (kt < last_kt) { fill(kt + 1, buf ^ 1); CP_WAIT1(); }
        else              { CP_WAIT0(); }
        __syncthreads();

        if (k0 <= rw + 15) {
            const uint32_t st = smb + buf * AT_STAGE;

            // ---- S = Q K^T (2-pass: qh*kh + qh*kl) ----
            float s[8][4];
#pragma unroll
            for (int ni = 0; ni < 8; ni++)
#pragma unroll
                for (int e = 0; e < 4; e++) s[ni][e] = 0.f;

#pragma unroll
            for (int nj = 0; nj < 4; nj++) {
                const uint32_t roff = (uint32_t)((16 * nj + brow) * KPITCH + bcol);
#pragma unroll
                for (int kf = 0; kf < 8; kf++) {
                    uint32_t addr = st + AT_OFF_KHI + roff + kf * 32;
                    uint32_t bh[4], bl[4];
                    LDM4(bh, addr);
                    LDM4(bl, addr + (AT_OFF_KLO - AT_OFF_KHI));
                    MMA16816(s[2 * nj],     qh[kf], bh);
                    MMA16816(s[2 * nj + 1], qh[kf], bh + 2);
                    MMA16816(s[2 * nj],     qh[kf], bl);
                    MMA16816(s[2 * nj + 1], qh[kf], bl + 2);
                }
            }

            // ---- mask ----
            const float* pf = padS + buf * 64;
            const bool causal = (k0 + 63 > rw);
            const int rg = rw + g, rg8 = rg + 8;
#pragma unroll
            for (int ni = 0; ni < 8; ni++) {
                int c0 = ni * 8 + 2 * t, c1 = c0 + 1;
                bool p0 = pf[c0] < 0.5f, p1 = pf[c1] < 0.5f;
                bool ok0 = p0, ok1 = p1, ok2 = p0, ok3 = p1;
                if (causal) {
                    ok0 = ok0 && (k0 + c0 <= rg);
                    ok1 = ok1 && (k0 + c1 <= rg);
                    ok2 = ok2 && (k0 + c0 <= rg8);
                    ok3 = ok3 && (k0 + c1 <= rg8);
                }
                s[ni][0] = ok0 ? s[ni][0] : -INFINITY;
                s[ni][1] = ok1 ? s[ni][1] : -INFINITY;
                s[ni][2] = ok2 ? s[ni][2] : -INFINITY;
                s[ni][3] = ok3 ? s[ni][3] : -INFINITY;
            }

            // ---- online softmax, base-2 ----
            float rm0 = -INFINITY, rm1 = -INFINITY;
#pragma unroll
            for (int ni = 0; ni < 8; ni++) {
                rm0 = fmaxf(rm0, fmaxf(s[ni][0], s[ni][1]));
                rm1 = fmaxf(rm1, fmaxf(s[ni][2], s[ni][3]));
            }
            rm0 = fmaxf(rm0, __shfl_xor_sync(0xffffffffu, rm0, 1));
            rm0 = fmaxf(rm0, __shfl_xor_sync(0xffffffffu, rm0, 2));
            rm1 = fmaxf(rm1, __shfl_xor_sync(0xffffffffu, rm1, 1));
            rm1 = fmaxf(rm1, __shfl_xor_sync(0xffffffffu, rm1, 2));
            float mn0 = fmaxf(m0, rm0), mn1 = fmaxf(m1, rm1);
            float a0 = ex2f(m0 - mn0), a1 = ex2f(m1 - mn1);
            m0 = mn0; m1 = mn1;

            float ls0 = 0.f, ls1 = 0.f;
#pragma unroll
            for (int ni = 0; ni < 8; ni++) {
                s[ni][0] = ex2f(s[ni][0] - m0); ls0 += s[ni][0];
                s[ni][1] = ex2f(s[ni][1] - m0); ls0 += s[ni][1];
                s[ni][2] = ex2f(s[ni][2] - m1); ls1 += s[ni][2];
                s[ni][3] = ex2f(s[ni][3] - m1); ls1 += s[ni][3];
            }
            ls0 += __shfl_xor_sync(0xffffffffu, ls0, 1);
            ls0 += __shfl_xor_sync(0xffffffffu, ls0, 2);
            ls1 += __shfl_xor_sync(0xffffffffu, ls1, 1);
            ls1 += __shfl_xor_sync(0xffffffffu, ls1, 2);
            l0 = l0 * a0 + ls0;
            l1 = l1 * a1 + ls1;
#pragma unroll
            for (int oj = 0; oj < 16; oj++) {
                o[oj][0] *= a0; o[oj][1] *= a0;
                o[oj][2] *= a1; o[oj][3] *= a1;
            }

            // ---- PV (2-pass: ph*vh + ph*vl) ----
#pragma unroll
            for (int kf = 0; kf < 4; kf++) {
                uint32_t ph[4];
                ph[0] = pack_h2(s[2 * kf][0],     s[2 * kf][1]);
                ph[1] = pack_h2(s[2 * kf][2],     s[2 * kf][3]);
                ph[2] = pack_h2(s[2 * kf + 1][0], s[2 * kf + 1][1]);
                ph[3] = pack_h2(s[2 * kf + 1][2], s[2 * kf + 1][3]);
#pragma unroll
                for (int dj = 0; dj < 8; dj++) {
                    uint32_t addr = st + AT_OFF_VTHI +
                        (uint32_t)((16 * dj + brow) * VPITCH + kf * 32 + bcol);
                    uint32_t vh[4], vl[4];
                    LDM4(vh, addr);
                    LDM4(vl, addr + (AT_OFF_VTLO - AT_OFF_VTHI));
                    MMA16816(o[2 * dj],     ph, vh);
                    MMA16816(o[2 * dj + 1], ph, vh + 2);
                    MMA16816(o[2 * dj],     ph, vl);
                    MMA16816(o[2 * dj + 1], ph, vl + 2);
                }
            }
        }
        __syncthreads();
    }

    // ---- epilogue: normalize, split fp16 hi/lo for O projection ----
    {
        float i0 = 1.f / l0, i1 = 1.f / l1;
        const size_t r0 = (size_t)(b * SEQ + rw + g) * HIDDEN + h * HDIM;
        const size_t r8 = r0 + (size_t)8 * HIDDEN;
#pragma unroll
        for (int oj = 0; oj < 16; oj++) {
            int c0 = oj * 8 + 2 * t;
            float v0 = o[oj][0] * i0, v1 = o[oj][1] * i0;
            float v2 = o[oj][2] * i1, v3 = o[oj][3] * i1;
            uint32_t h0 = pack_h2(v0, v1);
            uint32_t l0p = pack_h2(v0 - h2lo(h0), v1 - h2hi(h0));
            uint32_t h1 = pack_h2(v2, v3);
            uint32_t l1p = pack_h2(v2 - h2lo(h1), v3 - h2hi(h1));
            *(uint32_t*)((char*)g_ahi + (r0 + c0) * 2) = h0;
            *(uint32_t*)((char*)g_alo + (r0 + c0) * 2) = l0p;
            *(uint32_t*)((char*)g_ahi + (r8 + c0) * 2) = h1;
            *(uint32_t*)((char*)g_alo + (r8 + c0) * 2) = l1p;
        }
    }
}

// ================= launch =================
extern "C" void kernel_launch(void* const* d_in, const int* in_sizes, int n_in,
                              void* d_out, int out_size)
{
    (void)in_sizes; (void)n_in; (void)out_size;

    const float* X   = (const float*)d_in[0];
    const float* pad = (const float*)d_in[2];
    const float* Wq  = (const float*)d_in[3];
    const float* bq  = (const float*)d_in[4];
    const float* Wk  = (const float*)d_in[5];
    const float* bk  = (const float*)d_in[6];
    const float* Wv  = (const float*)d_in[7];
    const float* bv  = (const float*)d_in[8];
    const float* Wo  = (const float*)d_in[9];
    const float* bo  = (const float*)d_in[10];
    float* out = (float*)d_out;

    float* bqkvp;
    __half *xhi, *xlo, *qkvhi, *qkvlo, *ahi, *alo;
    __half *wth, *wtl, *woh, *wol;
    cudaGetSymbolAddress((void**)&bqkvp, g_bqkv);
    cudaGetSymbolAddress((void**)&xhi, g_xhi);
    cudaGetSymbolAddress((void**)&xlo, g_xlo);
    cudaGetSymbolAddress((void**)&qkvhi, g_qkvhi);
    cudaGetSymbolAddress((void**)&qkvlo, g_qkvlo);
    cudaGetSymbolAddress((void**)&ahi, g_ahi);
    cudaGetSymbolAddress((void**)&alo, g_alo);
    cudaGetSymbolAddress((void**)&wth, g_wT_hi);
    cudaGetSymbolAddress((void**)&wtl, g_wT_lo);
    cudaGetSymbolAddress((void**)&woh, g_woT_hi);
    cudaGetSymbolAddress((void**)&wol, g_woT_lo);

    cudaFuncSetAttribute(gemm_split<0>, cudaFuncAttributeMaxDynamicSharedMemorySize, GEMM_SMEM);
    cudaFuncSetAttribute(gemm_split<1>, cudaFuncAttributeMaxDynamicSharedMemorySize, GEMM_SMEM);
    cudaFuncSetAttribute(attn_tc, cudaFuncAttributeMaxDynamicSharedMemorySize, AT_SMEM);

    // --- prep ---
    {
        int n4 = MROWS * HIDDEN / 4;
        split_kernel<<<(n4 + 255) / 256, 256>>>(X, xhi, xlo, n4);
    }
    transpose_split<<<dim3(HIDDEN / 32, HIDDEN / 32), dim3(32, 8)>>>(Wq, wth, wtl, HIDDEN, HIDDEN);
    transpose_split<<<dim3(HDIM / 32,   HIDDEN / 32), dim3(32, 8)>>>(
        Wk, wth + (size_t)2048 * HIDDEN, wtl + (size_t)2048 * HIDDEN, HIDDEN, HDIM);
    transpose_split<<<dim3(HDIM / 32,   HIDDEN / 32), dim3(32, 8)>>>(
        Wv, wth + (size_t)2176 * HIDDEN, wtl + (size_t)2176 * HIDDEN, HIDDEN, HDIM);
    transpose_split<<<dim3(HIDDEN / 32, HIDDEN / 32), dim3(32, 8)>>>(Wo, woh, wol, HIDDEN, HIDDEN);
    pack_bias_qkv<<<9, 256>>>(bq, bk, bv);

    // --- fused QKV projection (Q pre-scaled by 1/sqrt(hd)*log2e) ---
    gemm_split<1><<<dim3(NQKV / 128, MROWS / 128), 256, GEMM_SMEM>>>(
        xhi, xlo, wth, wtl, bqkvp, nullptr, qkvhi, qkvlo, QSCALE, 2048, NQKV, HIDDEN);
    vt_prep<<<dim3(MROWS / 32, HDIM / 32), dim3(32, 8)>>>();

    // --- attention ---
    attn_tc<<<dim3(256, 1, BATCH), 256, AT_SMEM>>>(pad);

    // --- output projection ---
    gemm_split<0><<<dim3(HIDDEN / 128, MROWS / 128), 256, GEMM_SMEM>>>(
        ahi, alo, woh, wol, bo, out, nullptr, nullptr, 1.0f, 0, HIDDEN, HIDDEN);
}